// round 2
// baseline (speedup 1.0000x reference)
#include <cuda_runtime.h>

#define GN 4096   // N*N
#define TT 168    // T
#define BB 128    // B
#define NN 64     // N
#define PP 128    // P

#define MV_BLOCKS (GN / 2)            // 2 rows per block
#define TOTAL_A   (MV_BLOCKS + BB)    // + one y-block per batch

// Scratch (allocation-free rule: __device__ globals)
__device__ float d_v[GN];
__device__ float d_y[BB * NN];

__device__ __forceinline__ float dot4(float4 a, float4 b) {
    return a.x * b.x + a.y * b.y + a.z * b.z + a.w * b.w;
}

// ---------------------------------------------------------------------------
// Kernel A:
//  blocks [0, 2048): two matvec rows each: v[r] = g[r,:] . w^2, fused
//                    F[r,t] = v[r] * alpha[t]
//  blocks [2048, 2176): per-batch y[b,j] = sum_p x[b,j,p] * alpha[x_i[b,p]]
// ---------------------------------------------------------------------------
__global__ void __launch_bounds__(256) kA(const float* __restrict__ g,
                                          const float* __restrict__ w,
                                          const float* __restrict__ alphas,
                                          const float* __restrict__ x,
                                          const int*   __restrict__ xi,
                                          float* __restrict__ Fout) {
    const int blk = blockIdx.x;
    const int tid = threadIdx.x;

    if (blk < MV_BLOCKS) {
        const int row0 = blk * 2;
        const float4* __restrict__ g0 =
            reinterpret_cast<const float4*>(g + (size_t)row0 * GN);
        const float4* __restrict__ g1 =
            reinterpret_cast<const float4*>(g + (size_t)(row0 + 1) * GN);
        const float4* __restrict__ w4 = reinterpret_cast<const float4*>(w);

        // Front-batched independent loads: 12 in flight (MLP=12)
        float4 a0 = g0[tid];       float4 a1 = g0[tid + 256];
        float4 a2 = g0[tid + 512]; float4 a3 = g0[tid + 768];
        float4 b0 = g1[tid];       float4 b1 = g1[tid + 256];
        float4 b2 = g1[tid + 512]; float4 b3 = g1[tid + 768];
        float4 w0 = w4[tid];       float4 w1 = w4[tid + 256];
        float4 w2 = w4[tid + 512]; float4 w3 = w4[tid + 768];

        // Square w inline (k_w2 fused away)
        w0.x *= w0.x; w0.y *= w0.y; w0.z *= w0.z; w0.w *= w0.w;
        w1.x *= w1.x; w1.y *= w1.y; w1.z *= w1.z; w1.w *= w1.w;
        w2.x *= w2.x; w2.y *= w2.y; w2.z *= w2.z; w2.w *= w2.w;
        w3.x *= w3.x; w3.y *= w3.y; w3.z *= w3.z; w3.w *= w3.w;

        float s0 = (dot4(a0, w0) + dot4(a1, w1)) + (dot4(a2, w2) + dot4(a3, w3));
        float s1 = (dot4(b0, w0) + dot4(b1, w1)) + (dot4(b2, w2) + dot4(b3, w3));

        #pragma unroll
        for (int o = 16; o > 0; o >>= 1) {
            s0 += __shfl_xor_sync(0xffffffffu, s0, o);
            s1 += __shfl_xor_sync(0xffffffffu, s1, o);
        }

        __shared__ float red0[8], red1[8];
        __shared__ float vsh0, vsh1;
        if ((tid & 31) == 0) { red0[tid >> 5] = s0; red1[tid >> 5] = s1; }
        __syncthreads();
        if (tid == 0) {
            float t0 = 0.f, t1 = 0.f;
            #pragma unroll
            for (int i = 0; i < 8; i++) { t0 += red0[i]; t1 += red1[i]; }
            d_v[row0]     = t0;  vsh0 = t0;
            d_v[row0 + 1] = t1;  vsh1 = t1;
        }
        __syncthreads();

        if (tid < TT) {
            const float al = alphas[tid];
            Fout[(size_t)row0 * TT + tid]       = vsh0 * al;
            Fout[(size_t)(row0 + 1) * TT + tid] = vsh1 * al;
        }
    } else {
        // y-block: batch b
        const int b = blk - MV_BLOCKS;
        __shared__ float ap[PP];
        if (tid < PP)
            ap[tid] = alphas[xi[b * PP + tid]];
        __syncthreads();

        const int wid = tid >> 5, lane = tid & 31;
        #pragma unroll
        for (int j = wid; j < NN; j += 8) {
            const float* __restrict__ xr = x + ((size_t)b * NN + j) * PP;
            float s = xr[lane]      * ap[lane]
                    + xr[lane + 32] * ap[lane + 32]
                    + xr[lane + 64] * ap[lane + 64]
                    + xr[lane + 96] * ap[lane + 96];
            #pragma unroll
            for (int o = 16; o > 0; o >>= 1)
                s += __shfl_xor_sync(0xffffffffu, s, o);
            if (lane == 0) d_y[b * NN + j] = s;
        }
    }
}

// ---------------------------------------------------------------------------
// Kernel B: Z[b,i] = sum_j v[i*64+j] * y[b,j]
// v staged into padded smem (conflict-free); y to smem.
// ---------------------------------------------------------------------------
__global__ void __launch_bounds__(256) kB(float* __restrict__ Zout) {
    const int b = blockIdx.x;
    const int tid = threadIdx.x;
    __shared__ float sv[NN * 65];
    __shared__ float sy[NN];

    for (int i = tid; i < GN; i += 256)
        sv[(i >> 6) * 65 + (i & 63)] = d_v[i];
    if (tid < NN)
        sy[tid] = d_y[b * NN + tid];
    __syncthreads();

    if (tid < NN) {
        float s = 0.f;
        #pragma unroll
        for (int j = 0; j < NN; j++)
            s += sv[tid * 65 + j] * sy[j];
        Zout[b * NN + tid] = s;
    }
}

// ---------------------------------------------------------------------------
extern "C" void kernel_launch(void* const* d_in, const int* in_sizes, int n_in,
                              void* d_out, int out_size) {
    const float* x      = (const float*)d_in[0];   // [B, N, P]
    const int*   xi     = (const int*)  d_in[1];   // [B, P]
    const float* g      = (const float*)d_in[2];   // [N*N, N*N]
    const float* w      = (const float*)d_in[3];   // [N*N, 1]
    const float* alphas = (const float*)d_in[4];   // [1, T]

    float* out = (float*)d_out;
    float* Z = out;               // [B, N]   = 8192
    float* F = out + BB * NN;     // [N*N, T] = 688128

    kA<<<TOTAL_A, 256>>>(g, w, alphas, x, xi, F);
    kB<<<BB, 256>>>(Z);
}

// round 3
// speedup vs baseline: 2.0178x; 2.0178x over previous
#include <cuda_runtime.h>

#define GN 4096   // N*N
#define TT 168    // T
#define BB 128    // B
#define NN 64     // N
#define PP 128    // P

#define MV_BLOCKS (GN / 2)   // 2 rows per block

// Scratch (allocation-free rule: __device__ globals)
__device__ float d_v[GN];

__device__ __forceinline__ float dot4(float4 a, float4 b) {
    return a.x * b.x + a.y * b.y + a.z * b.z + a.w * b.w;
}

// ---------------------------------------------------------------------------
// Kernel 1: two matvec rows per block: v[r] = g[r,:] . w^2,
// fused epilogue F[r,t] = v[r] * alpha[t].
// K dimension split into two halves to cap live registers at 6 float4
// (24 regs) per phase -> no spills, good occupancy, MLP=6 per thread.
// ---------------------------------------------------------------------------
__global__ void __launch_bounds__(256) k_matvec(const float* __restrict__ g,
                                                const float* __restrict__ w,
                                                const float* __restrict__ alphas,
                                                float* __restrict__ Fout) {
    const int row0 = blockIdx.x * 2;
    const int tid  = threadIdx.x;
    const float4* __restrict__ g0 =
        reinterpret_cast<const float4*>(g + (size_t)row0 * GN);
    const float4* __restrict__ g1 =
        reinterpret_cast<const float4*>(g + (size_t)(row0 + 1) * GN);
    const float4* __restrict__ w4 = reinterpret_cast<const float4*>(w);

    float s0, s1;
    {   // ---- half 1: k in [0, 2048) ----
        float4 a0 = g0[tid];       float4 a1 = g0[tid + 256];
        float4 b0 = g1[tid];       float4 b1 = g1[tid + 256];
        float4 w0 = w4[tid];       float4 w1 = w4[tid + 256];
        w0.x *= w0.x; w0.y *= w0.y; w0.z *= w0.z; w0.w *= w0.w;
        w1.x *= w1.x; w1.y *= w1.y; w1.z *= w1.z; w1.w *= w1.w;
        s0 = dot4(a0, w0) + dot4(a1, w1);
        s1 = dot4(b0, w0) + dot4(b1, w1);
    }
    {   // ---- half 2: k in [2048, 4096) ----
        float4 a2 = g0[tid + 512]; float4 a3 = g0[tid + 768];
        float4 b2 = g1[tid + 512]; float4 b3 = g1[tid + 768];
        float4 w2 = w4[tid + 512]; float4 w3 = w4[tid + 768];
        w2.x *= w2.x; w2.y *= w2.y; w2.z *= w2.z; w2.w *= w2.w;
        w3.x *= w3.x; w3.y *= w3.y; w3.z *= w3.z; w3.w *= w3.w;
        s0 += dot4(a2, w2) + dot4(a3, w3);
        s1 += dot4(b2, w2) + dot4(b3, w3);
    }

    #pragma unroll
    for (int o = 16; o > 0; o >>= 1) {
        s0 += __shfl_xor_sync(0xffffffffu, s0, o);
        s1 += __shfl_xor_sync(0xffffffffu, s1, o);
    }

    __shared__ float red0[8], red1[8];
    __shared__ float vsh0, vsh1;
    if ((tid & 31) == 0) { red0[tid >> 5] = s0; red1[tid >> 5] = s1; }
    __syncthreads();
    if (tid == 0) {
        float t0 = 0.f, t1 = 0.f;
        #pragma unroll
        for (int i = 0; i < 8; i++) { t0 += red0[i]; t1 += red1[i]; }
        d_v[row0]     = t0;  vsh0 = t0;
        d_v[row0 + 1] = t1;  vsh1 = t1;
    }
    __syncthreads();

    if (tid < TT) {
        const float al = alphas[tid];
        Fout[(size_t)row0 * TT + tid]       = vsh0 * al;
        Fout[(size_t)(row0 + 1) * TT + tid] = vsh1 * al;
    }
}

// ---------------------------------------------------------------------------
// Kernel 2 (fused, Round-1 style): per batch b:
//   ap[p]  = alpha[x_i[b,p]]
//   y[j]   = sum_p x[b,j,p] * ap[p]          (DRAM traffic hides v-stage)
//   Z[b,i] = sum_j v[i*64+j] * y[j]
// v staged into padded smem (conflict-free GEMV); stage loop fully
// unrolled -> 16 independent L2 loads in flight per thread.
// ---------------------------------------------------------------------------
__global__ void __launch_bounds__(256) k_z(const float* __restrict__ x,
                                           const int* __restrict__ xi,
                                           const float* __restrict__ alphas,
                                           float* __restrict__ Zout) {
    const int b = blockIdx.x;
    const int tid = threadIdx.x;
    __shared__ float ap[PP];
    __shared__ float y[NN];
    __shared__ float sv[NN * 65];

    // Stage v (16 KB, L2-hot after k_matvec) into padded smem, MLP=16
    #pragma unroll
    for (int k = 0; k < 16; k++) {
        int i = tid + k * 256;
        sv[(i >> 6) * 65 + (i & 63)] = d_v[i];
    }

    if (tid < PP)
        ap[tid] = alphas[xi[b * PP + tid]];
    __syncthreads();

    const int wid = tid >> 5, lane = tid & 31;
    #pragma unroll
    for (int j = wid; j < NN; j += 8) {
        const float* __restrict__ xr = x + ((size_t)b * NN + j) * PP;
        float s = xr[lane]      * ap[lane]
                + xr[lane + 32] * ap[lane + 32]
                + xr[lane + 64] * ap[lane + 64]
                + xr[lane + 96] * ap[lane + 96];
        #pragma unroll
        for (int o = 16; o > 0; o >>= 1)
            s += __shfl_xor_sync(0xffffffffu, s, o);
        if (lane == 0) y[j] = s;
    }
    __syncthreads();

    if (tid < NN) {
        float s = 0.f;
        #pragma unroll
        for (int j = 0; j < NN; j++)
            s += sv[tid * 65 + j] * y[j];
        Zout[b * NN + tid] = s;
    }
}

// ---------------------------------------------------------------------------
extern "C" void kernel_launch(void* const* d_in, const int* in_sizes, int n_in,
                              void* d_out, int out_size) {
    const float* x      = (const float*)d_in[0];   // [B, N, P]
    const int*   xi     = (const int*)  d_in[1];   // [B, P]
    const float* g      = (const float*)d_in[2];   // [N*N, N*N]
    const float* w      = (const float*)d_in[3];   // [N*N, 1]
    const float* alphas = (const float*)d_in[4];   // [1, T]

    float* out = (float*)d_out;
    float* Z = out;               // [B, N]   = 8192
    float* F = out + BB * NN;     // [N*N, T] = 688128

    k_matvec<<<MV_BLOCKS, 256>>>(g, w, alphas, F);
    k_z<<<BB, 256>>>(x, xi, alphas, Z);
}

// round 4
// speedup vs baseline: 2.2757x; 1.1278x over previous
#include <cuda_runtime.h>

#define GN 4096   // N*N
#define TT 168    // T
#define BB 128    // B
#define NN 64     // N
#define PP 128    // P

#define ROWS_PER_BLK 8
#define MV_BLOCKS (GN / ROWS_PER_BLK)      // 512
#define TOTAL_K1  (MV_BLOCKS + BB)         // 512 + 128 = 640

#define ZB_BATCH 4
#define Z_BLOCKS (BB / ZB_BATCH)           // 32

// Scratch (allocation-free rule: __device__ globals)
__device__ float d_v[GN];
__device__ float d_y[BB * NN];

__device__ __forceinline__ float dot4(float4 a, float4 b) {
    return a.x * b.x + a.y * b.y + a.z * b.z + a.w * b.w;
}

// ---------------------------------------------------------------------------
// Kernel 1:
//  blocks [0, 512):  matvec, 8 rows per block, warp-per-row.
//    w^2 staged into smem ONCE per block (cuts redundant L2 w traffic 8x);
//    each lane streams 32 float4 of its g row from L2 (MLP 4-8 in flight).
//    Fused epilogue: d_v[row] and F[row, t] = v * alpha[t].
//  blocks [512, 640): per-batch y[b,j] = sum_p x[b,j,p] * alpha[x_i[b,p]].
//    Their DRAM traffic overlaps the matvec's L2 traffic.
// ---------------------------------------------------------------------------
__global__ void __launch_bounds__(256) k_main(const float* __restrict__ g,
                                              const float* __restrict__ w,
                                              const float* __restrict__ alphas,
                                              const float* __restrict__ x,
                                              const int*   __restrict__ xi,
                                              float* __restrict__ Fout) {
    __shared__ float ws[GN];     // matvec: w^2  |  y-block: ap[] aliases this
    __shared__ float sal[TT];

    const int blk  = blockIdx.x;
    const int tid  = threadIdx.x;
    const int wid  = tid >> 5;
    const int lane = tid & 31;

    if (blk < MV_BLOCKS) {
        // ---- stage w^2 into smem (16 KB), alphas (672 B) ----
        const float4* __restrict__ w4g = reinterpret_cast<const float4*>(w);
        float4* ws4 = reinterpret_cast<float4*>(ws);
        #pragma unroll
        for (int k = 0; k < 4; k++) {
            float4 t = w4g[tid + k * 256];
            t.x *= t.x; t.y *= t.y; t.z *= t.z; t.w *= t.w;
            ws4[tid + k * 256] = t;
        }
        if (tid < TT) sal[tid] = alphas[tid];
        __syncthreads();

        // ---- warp-per-row dot product ----
        const int row = blk * ROWS_PER_BLK + wid;
        const float4* __restrict__ g4 =
            reinterpret_cast<const float4*>(g + (size_t)row * GN);

        float acc0 = 0.f, acc1 = 0.f, acc2 = 0.f, acc3 = 0.f;
        #pragma unroll
        for (int c = 0; c < 8; c++) {
            const int base = c * 128 + lane;          // float4 units
            float4 a0 = g4[base];       float4 a1 = g4[base + 32];
            float4 a2 = g4[base + 64];  float4 a3 = g4[base + 96];
            float4 b0 = ws4[base];      float4 b1 = ws4[base + 32];
            float4 b2 = ws4[base + 64]; float4 b3 = ws4[base + 96];
            acc0 += dot4(a0, b0);
            acc1 += dot4(a1, b1);
            acc2 += dot4(a2, b2);
            acc3 += dot4(a3, b3);
        }
        float s = (acc0 + acc1) + (acc2 + acc3);
        #pragma unroll
        for (int o = 16; o > 0; o >>= 1)
            s += __shfl_xor_sync(0xffffffffu, s, o);   // all lanes get sum

        if (lane == 0) d_v[row] = s;

        // ---- F epilogue: F[row, t] = v * alpha[t] ----
        float* __restrict__ Frow = Fout + (size_t)row * TT;
        #pragma unroll
        for (int t = lane; t < TT; t += 32)
            Frow[t] = s * sal[t];
    } else {
        // ---- y-block: batch b ----
        const int b = blk - MV_BLOCKS;
        float* ap = ws;   // reuse smem
        if (tid < PP)
            ap[tid] = alphas[xi[b * PP + tid]];
        __syncthreads();

        #pragma unroll
        for (int j = wid; j < NN; j += 8) {
            const float* __restrict__ xr = x + ((size_t)b * NN + j) * PP;
            float s = xr[lane]      * ap[lane]
                    + xr[lane + 32] * ap[lane + 32]
                    + xr[lane + 64] * ap[lane + 64]
                    + xr[lane + 96] * ap[lane + 96];
            #pragma unroll
            for (int o = 16; o > 0; o >>= 1)
                s += __shfl_xor_sync(0xffffffffu, s, o);
            if (lane == 0) d_y[b * NN + j] = s;
        }
    }
}

// ---------------------------------------------------------------------------
// Kernel 2: Z[b,i] = sum_j v[i*64+j] * y[b,j]
// 32 blocks x 4 batches: v staged once per block into padded smem
// (conflict-free), 1 output per thread.
// ---------------------------------------------------------------------------
__global__ void __launch_bounds__(256) k_z(float* __restrict__ Zout) {
    const int b0  = blockIdx.x * ZB_BATCH;
    const int tid = threadIdx.x;
    __shared__ float sv[NN * 65];
    __shared__ float sy[ZB_BATCH * NN];

    #pragma unroll
    for (int k = 0; k < 16; k++) {
        int i = tid + k * 256;
        sv[(i >> 6) * 65 + (i & 63)] = d_v[i];
    }
    sy[tid] = d_y[b0 * NN + tid];      // 4*64 = 256 = blockDim
    __syncthreads();

    const int bi = tid >> 6;           // 0..3
    const int i  = tid & 63;           // row
    float s = 0.f;
    #pragma unroll
    for (int j = 0; j < NN; j++)
        s += sv[i * 65 + j] * sy[bi * NN + j];
    Zout[(b0 + bi) * NN + i] = s;
}

// ---------------------------------------------------------------------------
extern "C" void kernel_launch(void* const* d_in, const int* in_sizes, int n_in,
                              void* d_out, int out_size) {
    const float* x      = (const float*)d_in[0];   // [B, N, P]
    const int*   xi     = (const int*)  d_in[1];   // [B, P]
    const float* g      = (const float*)d_in[2];   // [N*N, N*N]
    const float* w      = (const float*)d_in[3];   // [N*N, 1]
    const float* alphas = (const float*)d_in[4];   // [1, T]

    float* out = (float*)d_out;
    float* Z = out;               // [B, N]   = 8192
    float* F = out + BB * NN;     // [N*N, T] = 688128

    k_main<<<TOTAL_K1, 256>>>(g, w, alphas, x, xi, F);
    k_z<<<Z_BLOCKS, 256>>>(Z);
}